// round 1
// baseline (speedup 1.0000x reference)
#include <cuda_runtime.h>

// UnifiedQuantumRegressor — fused 3-layer MLP + global reduction.
//
// Key algebraic fact: in the reference, every graph edge weight is 1.0, so
// wsum == float(deg) and mean_w = where(deg>0, deg/deg, 1.0) == 1.0 exactly.
// Hence attn == q_out and the entire O(N^2) fidelity Gram matrix is dead code.
// out = (sum_i tanh(relu(relu(s_i@W1+b1)@W2+b2)@Wq+bq)) @ Wh + bh   (scalar)

#define TM       16        // rows per block
#define NTHREADS 256
#define NBLK     512       // 8192 / TM

__device__ float g_partials[NBLK];

__global__ __launch_bounds__(NTHREADS) void fused_mlp_kernel(
    const float* __restrict__ S,   // [8192,512]
    const float* __restrict__ W1,  // [512,256]
    const float* __restrict__ b1,  // [256]
    const float* __restrict__ W2,  // [256,256]
    const float* __restrict__ b2,  // [256]
    const float* __restrict__ Wq,  // [256,64]
    const float* __restrict__ bq,  // [64]
    const float* __restrict__ Wh)  // [64,1]
{
    __shared__ float sA[TM * 512]; // 32KB: S tile; reused as enc2 [16][256]
    __shared__ float sE[TM * 256]; // 16KB: enc1 [16][256]; reused as reduce scratch

    const int tid  = threadIdx.x;
    const int row0 = blockIdx.x * TM;

    // ---- load S tile [16 x 512] (coalesced float4) ----
    {
        const float4* src = (const float4*)(S + (size_t)row0 * 512);
        float4* dst = (float4*)sA;
        #pragma unroll
        for (int i = 0; i < (TM * 512 / 4) / NTHREADS; ++i)   // 8 iters
            dst[tid + i * NTHREADS] = src[tid + i * NTHREADS];
    }
    __syncthreads();

    const int rg = tid >> 6;   // 0..3  -> rows rg*4 .. rg*4+3
    const int cg = tid & 63;   // cols cg*4 .. cg*4+3

    // ---- stage 1: enc1 = relu(S @ W1 + b1), [16 x 256] ----
    float acc[4][4];
    #pragma unroll
    for (int r = 0; r < 4; ++r)
        #pragma unroll
        for (int j = 0; j < 4; ++j) acc[r][j] = 0.f;

    #pragma unroll 4
    for (int k = 0; k < 512; ++k) {
        const float4 w = *(const float4*)(W1 + k * 256 + cg * 4);
        #pragma unroll
        for (int r = 0; r < 4; ++r) {
            const float s = sA[(rg * 4 + r) * 512 + k];  // broadcast LDS
            acc[r][0] += s * w.x;
            acc[r][1] += s * w.y;
            acc[r][2] += s * w.z;
            acc[r][3] += s * w.w;
        }
    }
    {
        const float4 bb = *(const float4*)(b1 + cg * 4);
        #pragma unroll
        for (int r = 0; r < 4; ++r) {
            float4 v;
            v.x = fmaxf(acc[r][0] + bb.x, 0.f);
            v.y = fmaxf(acc[r][1] + bb.y, 0.f);
            v.z = fmaxf(acc[r][2] + bb.z, 0.f);
            v.w = fmaxf(acc[r][3] + bb.w, 0.f);
            *(float4*)(sE + (rg * 4 + r) * 256 + cg * 4) = v;
        }
    }
    __syncthreads();

    // ---- stage 2: enc2 = relu(enc1 @ W2 + b2), [16 x 256] -> into sA ----
    #pragma unroll
    for (int r = 0; r < 4; ++r)
        #pragma unroll
        for (int j = 0; j < 4; ++j) acc[r][j] = 0.f;

    #pragma unroll 4
    for (int k = 0; k < 256; ++k) {
        const float4 w = *(const float4*)(W2 + k * 256 + cg * 4);
        #pragma unroll
        for (int r = 0; r < 4; ++r) {
            const float s = sE[(rg * 4 + r) * 256 + k];
            acc[r][0] += s * w.x;
            acc[r][1] += s * w.y;
            acc[r][2] += s * w.z;
            acc[r][3] += s * w.w;
        }
    }
    {
        const float4 bb = *(const float4*)(b2 + cg * 4);
        #pragma unroll
        for (int r = 0; r < 4; ++r) {
            float4 v;
            v.x = fmaxf(acc[r][0] + bb.x, 0.f);
            v.y = fmaxf(acc[r][1] + bb.y, 0.f);
            v.z = fmaxf(acc[r][2] + bb.z, 0.f);
            v.w = fmaxf(acc[r][3] + bb.w, 0.f);
            *(float4*)(sA + (rg * 4 + r) * 256 + cg * 4) = v;  // enc2 tile
        }
    }
    __syncthreads();

    // ---- stage 3: q = tanh(enc2 @ Wq + bq); h = q . Wh ----
    const int rg3 = tid >> 4;  // 0..15: one row
    const int cg3 = tid & 15;  // cols cg3*4 .. cg3*4+3

    float a3[4] = {0.f, 0.f, 0.f, 0.f};
    #pragma unroll 4
    for (int k = 0; k < 256; ++k) {
        const float4 w = *(const float4*)(Wq + k * 64 + cg3 * 4);
        const float s = sA[rg3 * 256 + k];
        a3[0] += s * w.x;
        a3[1] += s * w.y;
        a3[2] += s * w.z;
        a3[3] += s * w.w;
    }
    const float4 bqv = *(const float4*)(bq + cg3 * 4);
    const float4 whv = *(const float4*)(Wh + cg3 * 4);
    float p = tanhf(a3[0] + bqv.x) * whv.x
            + tanhf(a3[1] + bqv.y) * whv.y
            + tanhf(a3[2] + bqv.z) * whv.z
            + tanhf(a3[3] + bqv.w) * whv.w;

    // ---- block reduce (deterministic) ----
    #pragma unroll
    for (int o = 16; o > 0; o >>= 1)
        p += __shfl_down_sync(0xffffffffu, p, o);
    if ((tid & 31) == 0) sE[tid >> 5] = p;   // 8 warp partials
    __syncthreads();
    if (tid == 0) {
        float t = 0.f;
        #pragma unroll
        for (int i = 0; i < NTHREADS / 32; ++i) t += sE[i];
        g_partials[blockIdx.x] = t;
    }
}

__global__ __launch_bounds__(NBLK) void final_reduce_kernel(
    const float* __restrict__ bh, float* __restrict__ out)
{
    __shared__ float red[NBLK / 32];  // 16 warp partials
    const int tid = threadIdx.x;      // 512 threads
    float v = g_partials[tid];
    #pragma unroll
    for (int o = 16; o > 0; o >>= 1)
        v += __shfl_down_sync(0xffffffffu, v, o);
    if ((tid & 31) == 0) red[tid >> 5] = v;
    __syncthreads();
    if (tid < 32) {
        float t = (tid < NBLK / 32) ? red[tid] : 0.f;
        #pragma unroll
        for (int o = 8; o > 0; o >>= 1)
            t += __shfl_down_sync(0xffffffffu, t, o);
        if (tid == 0) out[0] = t + bh[0];
    }
}

extern "C" void kernel_launch(void* const* d_in, const int* in_sizes, int n_in,
                              void* d_out, int out_size)
{
    const float* S  = (const float*)d_in[0];
    const float* W1 = (const float*)d_in[1];
    const float* b1 = (const float*)d_in[2];
    const float* W2 = (const float*)d_in[3];
    const float* b2 = (const float*)d_in[4];
    const float* Wq = (const float*)d_in[5];
    const float* bq = (const float*)d_in[6];
    const float* Wh = (const float*)d_in[7];
    const float* bh = (const float*)d_in[8];
    float* out = (float*)d_out;

    fused_mlp_kernel<<<NBLK, NTHREADS>>>(S, W1, b1, W2, b2, Wq, bq, Wh);
    final_reduce_kernel<<<1, NBLK>>>(bh, out);
}